// round 1
// baseline (speedup 1.0000x reference)
#include <cuda_runtime.h>

// ---------------- problem constants ----------------
constexpr int KT = 4, KB = 16, KC = 384, KN = 256, KH = 8, KD = 48;
constexpr int SZ_XT = KB * KC * KN;        // 1,572,864  (one time-slice, channel layout)
constexpr int SZ_X  = KT * SZ_XT;          // 6,291,456
constexpr int ATT_T = KB * KH * KN * KN;   // 8,388,608  (one time-slice of attn)
constexpr long long SZ_ATT = (long long)KT * ATT_T;     // 33,554,432
constexpr int SZ_COL = KC * 5 * KB * KN;   // 1920*4096 = 7,864,320
constexpr int SZ_CB  = KC * KB * KN;       // 384*4096  = 1,572,864

// ---------------- device scratch (static: allocation-free) ----------------
__device__ float g_xs[SZ_X];      // binary shortcut spikes, [t][b][c][n]
__device__ float g_q [SZ_X];      // q path (pre-act -> spikes -> tim -> final q)
__device__ float g_k [SZ_X];
__device__ float g_v [SZ_X];
__device__ float g_qh[SZ_X];      // q head layout [t][b][h][n][d]
__device__ float g_kt[SZ_X];      // k_t   [t][b][h][e][m]
__device__ float g_vt[SZ_X];      // v_t   [t][b][h][m][e]
__device__ float g_oh[SZ_X];      // out heads [t][b][h][n][d]
__device__ float g_o [SZ_X];      // out channel layout + identity
__device__ float g_p [SZ_X];      // proj pre-activation
__device__ float g_to[SZ_X];      // tim "outs" stack
__device__ float g_xt[SZ_XT];     // tim recurrent state [b][c][n]
__device__ float g_col[SZ_COL];   // im2col buffer [ci*5+kk][b*256+n]
__device__ float g_cb [SZ_CB];    // tim conv output [co][b*256+n]
__device__ float g_attn[SZ_ATT];  // attn / attn_map [t][b][h][n][m]

__device__ float g_wkf[KC*KC], g_wvf[KC*KC], g_wpf[KC*KC];
__device__ float g_bk[KC], g_bv[KC], g_bp[KC];
__device__ float g_dw[KD*KD], g_dwT[KD*KD], g_db[KD];
__device__ float g_cnt[1], g_c1[1];

// ---------------- generic tiled fp32 GEMM: C = A[M,K] * B[K,N] (+bias) ----------------
// biasMode: 0 none, 1 per-row(M), 2 per-col(N). All dims exactly divisible by tiles.
template<int BM,int BN,int BK,int TM,int TN>
__global__ void sgemm(int M,int N,int K,
    const float* __restrict__ A, int lda, long long sA,
    const float* __restrict__ B, int ldb, long long sB,
    float* __restrict__ C, int ldc, long long sC,
    const float* __restrict__ bias, int biasMode)
{
    constexpr int TX = BN / TN, TY = BM / TM, NT = TX * TY;
    __shared__ float As[BK][BM + 4];
    __shared__ float Bs[BK][BN + 4];
    int bi = blockIdx.z;
    A += (size_t)bi * sA;  B += (size_t)bi * sB;  C += (size_t)bi * sC;
    const int tx = threadIdx.x, ty = threadIdx.y;
    const int tid = ty * TX + tx;
    const int row0 = blockIdx.y * BM, col0 = blockIdx.x * BN;

    float acc[TM][TN];
#pragma unroll
    for (int i = 0; i < TM; i++)
#pragma unroll
        for (int j = 0; j < TN; j++) acc[i][j] = 0.f;

    for (int k0 = 0; k0 < K; k0 += BK) {
        for (int idx = tid; idx < BM * BK; idx += NT) {
            int kk = idx % BK, m = idx / BK;
            As[kk][m] = A[(size_t)(row0 + m) * lda + (k0 + kk)];
        }
        for (int idx = tid; idx < BK * BN; idx += NT) {
            int n = idx % BN, kk = idx / BN;
            Bs[kk][n] = B[(size_t)(k0 + kk) * ldb + (col0 + n)];
        }
        __syncthreads();
#pragma unroll
        for (int kk = 0; kk < BK; kk++) {
            float a[TM], b[TN];
#pragma unroll
            for (int i = 0; i < TM; i++) a[i] = As[kk][ty * TM + i];
#pragma unroll
            for (int j = 0; j < TN; j++) b[j] = Bs[kk][tx * TN + j];
#pragma unroll
            for (int i = 0; i < TM; i++)
#pragma unroll
                for (int j = 0; j < TN; j++)
                    acc[i][j] = fmaf(a[i], b[j], acc[i][j]);
        }
        __syncthreads();
    }
#pragma unroll
    for (int i = 0; i < TM; i++) {
        int r = row0 + ty * TM + i;
        float bv = 0.f;
        if (biasMode == 1) bv = bias[r];
#pragma unroll
        for (int j = 0; j < TN; j++) {
            int cn = col0 + tx * TN + j;
            float val = acc[i][j] + bv;
            if (biasMode == 2) val += bias[cn];
            C[(size_t)r * ldc + cn] = val;
        }
    }
}

// ---------------- weight folding (fold inference BN into weights/bias) ----------------
__global__ void fold_weights(const float* __restrict__ wk, const float* __restrict__ wv,
                             const float* __restrict__ pw, const float* __restrict__ pb,
                             const float* __restrict__ kbn, const float* __restrict__ vbn,
                             const float* __restrict__ pbn, const float* __restrict__ dstw,
                             const float* __restrict__ dbn)
{
    int i = blockIdx.x * blockDim.x + threadIdx.x;
    if (i == 0) g_cnt[0] = 0.f;
    if (i < KC * KC) {
        int d = i / KC;
        float invk = kbn[d] * rsqrtf(kbn[3*KC + d] + 1e-5f);
        float invv = vbn[d] * rsqrtf(vbn[3*KC + d] + 1e-5f);
        float invp = pbn[d] * rsqrtf(pbn[3*KC + d] + 1e-5f);
        g_wkf[i] = invk * wk[i];
        g_wvf[i] = invv * wv[i];
        g_wpf[i] = invp * pw[i];
    }
    if (i < KC) {
        float invk = kbn[i] * rsqrtf(kbn[3*KC + i] + 1e-5f);
        float invv = vbn[i] * rsqrtf(vbn[3*KC + i] + 1e-5f);
        float invp = pbn[i] * rsqrtf(pbn[3*KC + i] + 1e-5f);
        g_bk[i] = kbn[KC + i] - invk * kbn[2*KC + i];
        g_bv[i] = vbn[KC + i] - invv * vbn[2*KC + i];
        g_bp[i] = pbn[KC + i] + invp * (pb[i] - pbn[2*KC + i]);
    }
    if (i < KD * KD) {
        int e = i / KD, d = i % KD;
        float inv = dbn[e] * rsqrtf(dbn[3*KD + e] + 1e-5f);
        float wf = inv * dstw[i];
        g_dw[i] = wf;
        g_dwT[d * KD + e] = wf;
    }
    if (i < KD) {
        float inv = dbn[i] * rsqrtf(dbn[3*KD + i] + 1e-5f);
        g_db[i] = dbn[KD + i] - inv * dbn[2*KD + i];
    }
}

// ---------------- LIF kernels (membrane carried in registers across T) ----------------
__global__ void lif_in(const float* __restrict__ x)
{
    int i = blockIdx.x * blockDim.x + threadIdx.x;
    if (i >= SZ_XT) return;
    float v = 0.f;
#pragma unroll
    for (int t = 0; t < KT; t++) {
        float xv = x[(size_t)t * SZ_XT + i];
        v += (xv - v) * 0.5f;
        float s = (v >= 1.0f) ? 1.f : 0.f;
        g_xs[(size_t)t * SZ_XT + i] = s;
        v *= (1.f - s);
    }
}

// in-place LIF over T, optional scale (attn uses *c1)
__global__ void lif4s(float* __restrict__ buf, float vth, int per_t, int tstride,
                      const float* __restrict__ scale)
{
    int i = blockIdx.x * blockDim.x + threadIdx.x;
    if (i >= per_t) return;
    float c = scale ? scale[0] : 1.0f;
    float v = 0.f;
#pragma unroll
    for (int t = 0; t < KT; t++) {
        float xv = buf[(size_t)t * tstride + i] * c;
        v += (xv - v) * 0.5f;
        float s = (v >= vth) ? 1.f : 0.f;
        buf[(size_t)t * tstride + i] = s;
        v *= (1.f - s);
    }
}

// ---------------- TIM kernels ----------------
__global__ void tim_init()   // outs[0] = x_tim = q_s[0]
{
    int i = blockIdx.x * blockDim.x + threadIdx.x;
    if (i >= SZ_XT) return;
    float v = g_q[i];
    g_xt[i] = v;
    g_to[i] = v;
}

__global__ void im2col_k()
{
    int i = blockIdx.x * blockDim.x + threadIdx.x;
    if (i >= SZ_COL) return;
    int j  = i & 4095;           // b*256+n
    int r  = i >> 12;            // ci*5+kk
    int kk = r % 5, ci = r / 5;
    int b = j >> 8, n = j & 255;
    int n2 = n + kk - 2;
    float val = (n2 >= 0 && n2 < KN) ? g_xt[(size_t)(b * KC + ci) * KN + n2] : 0.f;
    g_col[i] = val;
}

__global__ void tim_update(int ti)
{
    int i = blockIdx.x * blockDim.x + threadIdx.x;
    if (i >= SZ_XT) return;
    int n  = i & 255;
    int co = (i >> 8) % KC;
    int b  = i / (KC * KN);
    float c = g_cb[(size_t)co * 4096 + b * 256 + n];
    float s = (c * 0.5f >= 0.3f) ? 1.f : 0.f;            // single-step LIF, vth 0.3
    float xt = s * 0.6f + g_q[(size_t)ti * SZ_XT + i] * 0.4f;
    g_xt[i] = xt;
    g_to[(size_t)ti * SZ_XT + i] = xt;
}

__global__ void tim_final_lif()  // output LIF (vth 0.5) + spike count for c1
{
    int i = blockIdx.x * blockDim.x + threadIdx.x;
    int cnt = 0;
    if (i < SZ_XT) {
        float v = 0.f;
#pragma unroll
        for (int t = 0; t < KT; t++) {
            float xv = g_to[(size_t)t * SZ_XT + i];
            v += (xv - v) * 0.5f;
            float s = (v >= 0.5f) ? 1.f : 0.f;
            g_q[(size_t)t * SZ_XT + i] = s;
            cnt += (int)s;
            v *= (1.f - s);
        }
    }
#pragma unroll
    for (int o = 16; o > 0; o >>= 1) cnt += __shfl_down_sync(0xffffffffu, cnt, o);
    if ((threadIdx.x & 31) == 0 && cnt) atomicAdd(&g_cnt[0], (float)cnt);
}

__global__ void c1_kernel()
{
    float mean = g_cnt[0] / 6291456.0f;
    g_c1[0] = fminf(1.0f / sqrtf(mean * 48.0f + 1e-6f), 10.0f);
}

// ---------------- head layout transforms ----------------
__global__ void make_qh()
{
    int i = blockIdx.x * blockDim.x + threadIdx.x;
    if (i >= SZ_X) return;
    int d = i % KD;
    int n = (i / KD) % KN;
    int h = (i / (KD * KN)) % KH;
    int tb = i / (KD * KN * KH);
    g_qh[i] = g_q[(size_t)(tb * KC + h * KD + d) * KN + n];
}

__global__ void make_vh(float* __restrict__ outv)   // also output #2 (v in head layout)
{
    int i = blockIdx.x * blockDim.x + threadIdx.x;
    if (i >= SZ_X) return;
    int d = i % KD;
    int n = (i / KD) % KN;
    int h = (i / (KD * KN)) % KH;
    int tb = i / (KD * KN * KH);
    outv[i] = g_v[(size_t)(tb * KC + h * KD + d) * KN + n];
}

// ---------------- tiny dst GEMMs (48x48) ----------------
__global__ void kt_gemm()   // kt[e][m] = sum_d dw[e][d] * k[d][m] + db[e]
{
    int bi = blockIdx.x;            // (t,b,h)
    int m  = threadIdx.x;           // 0..255
    __shared__ float A[KD * KD];
    __shared__ float bsh[KD];
    for (int idx = m; idx < KD * KD; idx += 256) A[idx] = g_dw[idx];
    if (m < KD) bsh[m] = g_db[m];
    __syncthreads();
    const float* Bp = g_k + (size_t)bi * (KD * KN);
    float kd[KD];
#pragma unroll
    for (int d = 0; d < KD; d++) kd[d] = Bp[d * KN + m];
    float* Cp = g_kt + (size_t)bi * (KD * KN);
#pragma unroll
    for (int e = 0; e < KD; e++) {
        float s = bsh[e];
#pragma unroll
        for (int d = 0; d < KD; d++) s = fmaf(A[e * KD + d], kd[d], s);
        Cp[e * KN + m] = s;
    }
}

__global__ void vt_gemm(const float* __restrict__ vh)  // vt[m][e] = sum_d vh[m][d]*dwT[d][e] + db[e]
{
    int bi = blockIdx.x;
    int m  = threadIdx.x;
    __shared__ float BT[KD * KD];
    __shared__ float bsh[KD];
    for (int idx = m; idx < KD * KD; idx += 256) BT[idx] = g_dwT[idx];
    if (m < KD) bsh[m] = g_db[m];
    __syncthreads();
    const float* row = vh + (size_t)bi * (KN * KD) + m * KD;
    float r[KD];
#pragma unroll
    for (int d = 0; d < KD; d++) r[d] = row[d];
    float* Cp = g_vt + (size_t)bi * (KN * KD) + m * KD;
#pragma unroll
    for (int e = 0; e < KD; e++) {
        float s = bsh[e];
#pragma unroll
        for (int d = 0; d < KD; d++) s = fmaf(r[d], BT[d * KD + e], s);
        Cp[e] = s;
    }
}

// ---------------- un-head + identity ----------------
__global__ void unhead(const float* __restrict__ x)
{
    int i = blockIdx.x * blockDim.x + threadIdx.x;
    if (i >= SZ_X) return;
    int n = i % KN;
    int c = (i / KN) % KC;
    int tb = i / (KC * KN);
    int h = c / KD, d = c % KD;
    g_o[i] = g_oh[((size_t)(tb * KH + h) * KN + n) * KD + d] + x[i];
}

__global__ void final_lif(float* __restrict__ out)
{
    int i = blockIdx.x * blockDim.x + threadIdx.x;
    if (i >= SZ_XT) return;
    float v = 0.f;
#pragma unroll
    for (int t = 0; t < KT; t++) {
        float xv = g_p[(size_t)t * SZ_XT + i];
        v += (xv - v) * 0.5f;
        float s = (v >= 1.0f) ? 1.f : 0.f;
        out[(size_t)t * SZ_XT + i] = s;
        v *= (1.f - s);
    }
}

// ---------------- host launcher ----------------
extern "C" void kernel_launch(void* const* d_in, const int* in_sizes, int n_in,
                              void* d_out, int out_size)
{
    (void)in_sizes; (void)n_in; (void)out_size;
    const float* x    = (const float*)d_in[0];
    const float* wq   = (const float*)d_in[1];
    const float* wk   = (const float*)d_in[2];
    const float* wv   = (const float*)d_in[3];
    const float* kbn  = (const float*)d_in[4];
    const float* vbn  = (const float*)d_in[5];
    const float* dstw = (const float*)d_in[6];
    const float* dbn  = (const float*)d_in[7];
    const float* pw   = (const float*)d_in[8];
    const float* pb   = (const float*)d_in[9];
    const float* pbn  = (const float*)d_in[10];
    const float* timw = (const float*)d_in[11];
    const float* timb = (const float*)d_in[12];
    float* out   = (float*)d_out;
    float* out_v = out + SZ_X;

    float *pxs, *pq, *pk, *pv, *pqh, *pkt, *pvt, *poh, *po, *pp;
    float *pcol, *pcb, *patt, *pwkf, *pwvf, *pwpf, *pbk, *pbv, *pbp, *pc1;
    cudaGetSymbolAddress((void**)&pxs,  g_xs);
    cudaGetSymbolAddress((void**)&pq,   g_q);
    cudaGetSymbolAddress((void**)&pk,   g_k);
    cudaGetSymbolAddress((void**)&pv,   g_v);
    cudaGetSymbolAddress((void**)&pqh,  g_qh);
    cudaGetSymbolAddress((void**)&pkt,  g_kt);
    cudaGetSymbolAddress((void**)&pvt,  g_vt);
    cudaGetSymbolAddress((void**)&poh,  g_oh);
    cudaGetSymbolAddress((void**)&po,   g_o);
    cudaGetSymbolAddress((void**)&pp,   g_p);
    cudaGetSymbolAddress((void**)&pcol, g_col);
    cudaGetSymbolAddress((void**)&pcb,  g_cb);
    cudaGetSymbolAddress((void**)&patt, g_attn);
    cudaGetSymbolAddress((void**)&pwkf, g_wkf);
    cudaGetSymbolAddress((void**)&pwvf, g_wvf);
    cudaGetSymbolAddress((void**)&pwpf, g_wpf);
    cudaGetSymbolAddress((void**)&pbk,  g_bk);
    cudaGetSymbolAddress((void**)&pbv,  g_bv);
    cudaGetSymbolAddress((void**)&pbp,  g_bp);
    cudaGetSymbolAddress((void**)&pc1,  g_c1);

    const int TB = 256;
    fold_weights<<<(KC*KC + TB - 1) / TB, TB>>>(wk, wv, pw, pb, kbn, vbn, pbn, dstw, dbn);
    lif_in<<<SZ_XT / TB, TB>>>(x);

    // q/k/v 1x1 convs: per-(t,b) GEMM 384x256x384
    {
        dim3 blk(16, 16), grd(KN / 128, KC / 128, KT * KB);
        sgemm<128,128,8,8,8><<<grd, blk>>>(KC, KN, KC, wq,   KC, 0, pxs, KN, SZ_XT / KT * 0 + (long long)(KC * KN),
                                           pq, KN, (long long)(KC * KN), nullptr, 0);
        sgemm<128,128,8,8,8><<<grd, blk>>>(KC, KN, KC, pwkf, KC, 0, pxs, KN, (long long)(KC * KN),
                                           pk, KN, (long long)(KC * KN), pbk, 1);
        sgemm<128,128,8,8,8><<<grd, blk>>>(KC, KN, KC, pwvf, KC, 0, pxs, KN, (long long)(KC * KN),
                                           pv, KN, (long long)(KC * KN), pbv, 1);
    }

    lif4s<<<SZ_XT / TB, TB>>>(pq, 0.05f, SZ_XT, SZ_XT, nullptr);
    lif4s<<<SZ_XT / TB, TB>>>(pk, 1.0f,  SZ_XT, SZ_XT, nullptr);
    lif4s<<<SZ_XT / TB, TB>>>(pv, 1.0f,  SZ_XT, SZ_XT, nullptr);

    // ---- TIM: sequential over t = 1..3 ----
    tim_init<<<SZ_XT / TB, TB>>>();
    for (int ti = 1; ti < KT; ti++) {
        im2col_k<<<SZ_COL / TB, TB>>>();
        dim3 blk(16, 16), grd(4096 / 128, KC / 128, 1);
        sgemm<128,128,8,8,8><<<grd, blk>>>(KC, 4096, KC * 5, timw, KC * 5, 0,
                                           pcol, 4096, 0, pcb, 4096, 0, timb, 1);
        tim_update<<<SZ_XT / TB, TB>>>(ti);
    }
    tim_final_lif<<<SZ_XT / TB, TB>>>();
    c1_kernel<<<1, 1>>>();

    // ---- head transforms ----
    make_qh<<<SZ_X / TB, TB>>>();
    make_vh<<<SZ_X / TB, TB>>>(out_v);

    // ---- dst conv + shared BN ----
    kt_gemm<<<KT * KB * KH, 256>>>();
    vt_gemm<<<KT * KB * KH, 256>>>(out_v);

    // ---- attention scores: [256,48] x [48,256] per (t,b,h) ----
    {
        dim3 blk(16, 16), grd(KN / 64, KN / 64, KT * KB * KH);
        sgemm<64,64,16,4,4><<<grd, blk>>>(KN, KN, KD,
            pqh, KD, (long long)(KN * KD),
            pkt, KN, (long long)(KD * KN),
            patt, KN, (long long)(KN * KN), nullptr, 0);
    }
    lif4s<<<ATT_T / TB, TB>>>(patt, 0.5f, ATT_T, ATT_T, pc1);

    // ---- out = attn_map @ v_t : [256,256] x [256,48] per (t,b,h) ----
    {
        dim3 blk(16, 16), grd(KD / 48, KN / 64, KT * KB * KH);
        sgemm<64,48,16,4,3><<<grd, blk>>>(KN, KD, KN,
            patt, KN, (long long)(KN * KN),
            pvt, KD, (long long)(KN * KD),
            poh, KD, (long long)(KN * KD), nullptr, 0);
    }

    unhead<<<SZ_X / TB, TB>>>(x);

    // ---- proj + folded BN ----
    {
        dim3 blk(16, 16), grd(KN / 128, KC / 128, KT * KB);
        sgemm<128,128,8,8,8><<<grd, blk>>>(KC, KN, KC, pwpf, KC, 0, po, KN, (long long)(KC * KN),
                                           pp, KN, (long long)(KC * KN), pbp, 1);
    }
    final_lif<<<SZ_XT / TB, TB>>>(out);
}

// round 2
// speedup vs baseline: 2.5435x; 2.5435x over previous
#include <cuda_runtime.h>

// ---------------- problem constants ----------------
constexpr int KT = 4, KB = 16, KC = 384, KN = 256, KH = 8, KD = 48;
constexpr int COLS = KT * KB * KN;     // 16384 columns in blocked layout
constexpr int TCOL = KB * KN;          // 4096 per time step
constexpr int SZ_XT = KC * TCOL;       // 1,572,864
constexpr int SZ_X  = KC * COLS;       // 6,291,456
constexpr int ATT_T = KB * KH * KN * KN;              // 8,388,608
constexpr long long SZ_ATT = (long long)KT * ATT_T;   // 33,554,432
constexpr int SZ_COL = KC * 5 * TCOL;  // 7,864,320
constexpr int SZ_CB  = KC * TCOL;

// ---------------- device scratch ----------------
__device__ float g_xs [SZ_X];        // shortcut spikes, blocked [c][t*4096+b*256+n]
__device__ float g_qkv[3 * SZ_X];    // q | k | v, blocked layout
__device__ float g_xt [SZ_XT];       // tim recurrent state [c][4096]
__device__ float g_col[SZ_COL];      // im2col [ci*5+kk][4096]
__device__ float g_cb [SZ_CB];       // tim conv out [c][4096]
__device__ float g_kt [SZ_X];        // k_t  [z=(h,t,b)][e][m]
__device__ float g_vt [SZ_X];        // v_t  [z][m][e]
__device__ float g_attn[SZ_ATT];     // attn [h][t][b][n][m]
__device__ float g_oh [SZ_X];        // attn out [z][n][d]
__device__ float g_o  [SZ_X];        // out + identity, blocked
__device__ float g_p  [SZ_X];        // proj pre-act, blocked

__device__ float g_wqkv[3 * KC * KC];
__device__ float g_bqkv[3 * KC];
__device__ float g_wpf[KC * KC], g_bp[KC];
__device__ float g_dw[KD * KD], g_dwT[KD * KD], g_db[KD];
__device__ float g_cnt[1], g_c1[1];

// ---------------- double-buffered vectorized SGEMM ----------------
// C[M,N] = A*B (+bias per M-row). ATR=0: A[M,K] row-major. ATR=1: A[K,M].
// Batch z: A offset = (z>>shA)*sA1 + (z&((1<<shA)-1))*sA2; B,C linear strides.
template<int BM, int BN, int BK, int TM, int TN, int ATR>
__global__ void __launch_bounds__(256, 2)
gemm_k(int M, int N, int K,
       const float* __restrict__ A, int lda, int shA, long long sA1, long long sA2,
       const float* __restrict__ B, int ldb, long long sB,
       float* __restrict__ C, int ldc, long long sC,
       const float* __restrict__ bias)
{
    constexpr int TX = BN / TN, TY = BM / TM, NT = TX * TY;
    static_assert(NT == 256, "need 256 threads");
    constexpr int PAD = 4;
    constexpr int A4 = BM * BK / 4, B4 = BK * BN / 4;
    constexpr int APT = (A4 + NT - 1) / NT, BPT = (B4 + NT - 1) / NT;
    __shared__ __align__(16) float As[2][BK][BM + PAD];
    __shared__ __align__(16) float Bs[2][BK][BN];

    const int tx = threadIdx.x, ty = threadIdx.y;
    const int tid = ty * TX + tx;
    const int row0 = blockIdx.y * BM, col0 = blockIdx.x * BN;
    const int z = blockIdx.z;
    A += ((long long)(z >> shA)) * sA1 + (long long)(z & ((1 << shA) - 1)) * sA2;
    B += (long long)z * sB;
    C += (long long)z * sC;

    float4 aR[APT], bR[BPT];

    auto ldg = [&](int k0) {
#pragma unroll
        for (int u = 0; u < APT; u++) {
            int idx = tid + u * NT;
            if (A4 % NT == 0 || idx < A4) {
                if (ATR == 0) {
                    int r = idx / (BK / 4), c4 = idx % (BK / 4);
                    aR[u] = *(const float4*)&A[(long long)(row0 + r) * lda + k0 + c4 * 4];
                } else {
                    int kk = idx / (BM / 4), m4 = idx % (BM / 4);
                    aR[u] = *(const float4*)&A[(long long)(k0 + kk) * lda + row0 + m4 * 4];
                }
            }
        }
#pragma unroll
        for (int u = 0; u < BPT; u++) {
            int idx = tid + u * NT;
            if (B4 % NT == 0 || idx < B4) {
                int kk = idx / (BN / 4), n4 = idx % (BN / 4);
                bR[u] = *(const float4*)&B[(long long)(k0 + kk) * ldb + col0 + n4 * 4];
            }
        }
    };
    auto sts = [&](int buf) {
#pragma unroll
        for (int u = 0; u < APT; u++) {
            int idx = tid + u * NT;
            if (A4 % NT == 0 || idx < A4) {
                if (ATR == 0) {
                    int r = idx / (BK / 4), c4 = idx % (BK / 4);
                    As[buf][c4 * 4 + 0][r] = aR[u].x;
                    As[buf][c4 * 4 + 1][r] = aR[u].y;
                    As[buf][c4 * 4 + 2][r] = aR[u].z;
                    As[buf][c4 * 4 + 3][r] = aR[u].w;
                } else {
                    int kk = idx / (BM / 4), m4 = idx % (BM / 4);
                    *(float4*)&As[buf][kk][m4 * 4] = aR[u];
                }
            }
        }
#pragma unroll
        for (int u = 0; u < BPT; u++) {
            int idx = tid + u * NT;
            if (B4 % NT == 0 || idx < B4) {
                int kk = idx / (BN / 4), n4 = idx % (BN / 4);
                *(float4*)&Bs[buf][kk][n4 * 4] = bR[u];
            }
        }
    };

    float acc[TM][TN];
#pragma unroll
    for (int i = 0; i < TM; i++)
#pragma unroll
        for (int j = 0; j < TN; j++) acc[i][j] = 0.f;

    auto comp = [&](int buf) {
#pragma unroll
        for (int kk = 0; kk < BK; kk++) {
            float a[TM], b[TN];
            if (TM % 4 == 0) {
#pragma unroll
                for (int i4 = 0; i4 < TM / 4; i4++) {
                    float4 v = *(const float4*)&As[buf][kk][ty * TM + i4 * 4];
                    a[i4 * 4 + 0] = v.x; a[i4 * 4 + 1] = v.y;
                    a[i4 * 4 + 2] = v.z; a[i4 * 4 + 3] = v.w;
                }
            } else {
#pragma unroll
                for (int i = 0; i < TM; i++) a[i] = As[buf][kk][ty * TM + i];
            }
            if (TN % 4 == 0) {
#pragma unroll
                for (int j4 = 0; j4 < TN / 4; j4++) {
                    float4 v = *(const float4*)&Bs[buf][kk][tx * TN + j4 * 4];
                    b[j4 * 4 + 0] = v.x; b[j4 * 4 + 1] = v.y;
                    b[j4 * 4 + 2] = v.z; b[j4 * 4 + 3] = v.w;
                }
            } else {
#pragma unroll
                for (int j = 0; j < TN; j++) b[j] = Bs[buf][kk][tx * TN + j];
            }
#pragma unroll
            for (int i = 0; i < TM; i++)
#pragma unroll
                for (int j = 0; j < TN; j++)
                    acc[i][j] = fmaf(a[i], b[j], acc[i][j]);
        }
    };

    ldg(0); sts(0); __syncthreads();
    const int nit = K / BK;
    int buf = 0;
    for (int it = 1; it < nit; it++) {
        ldg(it * BK);
        comp(buf);
        sts(buf ^ 1);
        __syncthreads();
        buf ^= 1;
    }
    comp(buf);

#pragma unroll
    for (int i = 0; i < TM; i++) {
        int r = row0 + ty * TM + i;
        float bv = bias ? bias[r] : 0.f;
        if (TN % 4 == 0) {
#pragma unroll
            for (int j4 = 0; j4 < TN / 4; j4++) {
                float4 v;
                v.x = acc[i][j4 * 4 + 0] + bv;
                v.y = acc[i][j4 * 4 + 1] + bv;
                v.z = acc[i][j4 * 4 + 2] + bv;
                v.w = acc[i][j4 * 4 + 3] + bv;
                *(float4*)&C[(long long)r * ldc + col0 + tx * TN + j4 * 4] = v;
            }
        } else {
#pragma unroll
            for (int j = 0; j < TN; j++)
                C[(long long)r * ldc + col0 + tx * TN + j] = acc[i][j] + bv;
        }
    }
}

// ---------------- BN folding ----------------
__global__ void fold_weights(const float* __restrict__ wq, const float* __restrict__ wk,
                             const float* __restrict__ wv, const float* __restrict__ pw,
                             const float* __restrict__ pb, const float* __restrict__ kbn,
                             const float* __restrict__ vbn, const float* __restrict__ pbn,
                             const float* __restrict__ dstw, const float* __restrict__ dbn)
{
    int i = blockIdx.x * blockDim.x + threadIdx.x;
    if (i == 0) g_cnt[0] = 0.f;
    if (i < 3 * KC * KC) {
        int rr = i / KC, c = i % KC;
        float w;
        if (rr < KC) w = wq[rr * KC + c];
        else if (rr < 2 * KC) { int d = rr - KC;     w = kbn[d] * rsqrtf(kbn[3*KC + d] + 1e-5f) * wk[d * KC + c]; }
        else                  { int d = rr - 2 * KC; w = vbn[d] * rsqrtf(vbn[3*KC + d] + 1e-5f) * wv[d * KC + c]; }
        g_wqkv[i] = w;
    }
    if (i < KC * KC) {
        int d = i / KC;
        g_wpf[i] = pbn[d] * rsqrtf(pbn[3*KC + d] + 1e-5f) * pw[i];
    }
    if (i < 3 * KC) {
        float bvv;
        if (i < KC) bvv = 0.f;
        else if (i < 2 * KC) { int d = i - KC;     float inv = kbn[d] * rsqrtf(kbn[3*KC+d] + 1e-5f); bvv = kbn[KC + d] - inv * kbn[2*KC + d]; }
        else                 { int d = i - 2 * KC; float inv = vbn[d] * rsqrtf(vbn[3*KC+d] + 1e-5f); bvv = vbn[KC + d] - inv * vbn[2*KC + d]; }
        g_bqkv[i] = bvv;
    }
    if (i < KC) {
        float inv = pbn[i] * rsqrtf(pbn[3*KC + i] + 1e-5f);
        g_bp[i] = pbn[KC + i] + inv * (pb[i] - pbn[2*KC + i]);
    }
    if (i < KD * KD) {
        int e = i / KD, d = i % KD;
        float inv = dbn[e] * rsqrtf(dbn[3*KD + e] + 1e-5f);
        float wf = inv * dstw[i];
        g_dw[i] = wf;
        g_dwT[d * KD + e] = wf;
    }
    if (i < KD) {
        float inv = dbn[i] * rsqrtf(dbn[3*KD + i] + 1e-5f);
        g_db[i] = dbn[KD + i] - inv * dbn[2*KD + i];
    }
}

// ---------------- LIF kernels ----------------
__global__ void lif_in(const float* __restrict__ x)
{
    int i = blockIdx.x * blockDim.x + threadIdx.x;
    if (i >= SZ_XT) return;
    int c = i >> 12, j = i & 4095, b = j >> 8, n = j & 255;
    const float* xp = x + ((long long)b * KC + c) * KN + n;
    float* o = g_xs + (long long)c * COLS + j;
    float v = 0.f;
#pragma unroll
    for (int t = 0; t < KT; t++) {
        float xv = xp[(long long)t * KB * KC * KN];
        v += (xv - v) * 0.5f;
        float s = (v >= 1.f) ? 1.f : 0.f;
        o[t * TCOL] = s;
        v *= (1.f - s);
    }
}

// blocked LIF: addr = (i>>lg)*(2^lg * T) + t*2^lg + (i & (2^lg-1))
__global__ void lif_blk(float* __restrict__ buf, float vth, int per_t, int lg,
                        const float* __restrict__ scale)
{
    int i = blockIdx.x * blockDim.x + threadIdx.x;
    if (i >= per_t) return;
    long long inner = 1LL << lg;
    long long o = ((long long)(i >> lg)) * (inner * KT) + (i & ((int)inner - 1));
    float c = scale ? scale[0] : 1.0f;
    float v = 0.f;
#pragma unroll
    for (int t = 0; t < KT; t++) {
        long long a = o + (long long)t * inner;
        float xv = buf[a] * c;
        v += (xv - v) * 0.5f;
        float s = (v >= vth) ? 1.f : 0.f;
        buf[a] = s;
        v *= (1.f - s);
    }
}

// ---------------- TIM ----------------
__global__ void tim_init()
{
    int i = blockIdx.x * blockDim.x + threadIdx.x;
    if (i >= SZ_XT) return;
    int c = i >> 12, j = i & 4095;
    g_xt[i] = g_qkv[(long long)c * COLS + j];
}

__global__ void im2col_k()
{
    int i = blockIdx.x * blockDim.x + threadIdx.x;
    if (i >= SZ_COL) return;
    int j = i & 4095, r = i >> 12;
    int kk = r % 5, ci = r / 5;
    int n = j & 255;
    int n2 = n + kk - 2;
    float v = 0.f;
    if (n2 >= 0 && n2 < KN) v = g_xt[ci * TCOL + (j - n) + n2];
    g_col[i] = v;
}

__global__ void tim_update(int ti)
{
    int i = blockIdx.x * blockDim.x + threadIdx.x;
    if (i >= SZ_XT) return;
    int c = i >> 12, j = i & 4095;
    float cv = g_cb[i];
    float s = (cv * 0.5f >= 0.3f) ? 1.f : 0.f;     // single-step LIF, vth=0.3
    long long qa = (long long)c * COLS + ti * TCOL + j;
    float xt = s * 0.6f + g_qkv[qa] * 0.4f;
    g_xt[i] = xt;
    g_qkv[qa] = xt;                                 // outs written in-place
}

__global__ void tim_final()
{
    int i = blockIdx.x * blockDim.x + threadIdx.x;
    int cnt = 0;
    if (i < SZ_XT) {
        int c = i >> 12, j = i & 4095;
        float* q = g_qkv + (long long)c * COLS + j;
        float v = 0.f;
#pragma unroll
        for (int t = 0; t < KT; t++) {
            float xv = q[t * TCOL];
            v += (xv - v) * 0.5f;
            float s = (v >= 0.5f) ? 1.f : 0.f;
            q[t * TCOL] = s;
            cnt += (int)s;
            v *= (1.f - s);
        }
    }
#pragma unroll
    for (int o = 16; o > 0; o >>= 1) cnt += __shfl_down_sync(0xffffffffu, cnt, o);
    if ((threadIdx.x & 31) == 0 && cnt) atomicAdd(&g_cnt[0], (float)cnt);
}

__global__ void c1_kernel()
{
    float mean = g_cnt[0] / 6291456.0f;
    g_c1[0] = fminf(1.0f / sqrtf(mean * 48.0f + 1e-6f), 10.0f);
}

// ---------------- dst conv (48x48) on k / v ----------------
__global__ void kt_gemm()
{
    int z = blockIdx.x;                 // z = h*64 + t*16 + b
    int h = z >> 6, t = (z >> 4) & 3, b = z & 15;
    int m = threadIdx.x;
    __shared__ float A[KD * KD];
    __shared__ float bs[KD];
    for (int idx = m; idx < KD * KD; idx += 256) A[idx] = g_dw[idx];
    if (m < KD) bs[m] = g_db[m];
    __syncthreads();
    const float* kp = g_qkv + SZ_X + (long long)(h * KD) * COLS + t * TCOL + b * KN + m;
    float kd[KD];
#pragma unroll
    for (int d = 0; d < KD; d++) kd[d] = kp[(long long)d * COLS];
    float* Cp = g_kt + (long long)z * (KD * KN);
#pragma unroll
    for (int e = 0; e < KD; e++) {
        float s = bs[e];
#pragma unroll
        for (int d = 0; d < KD; d++) s = fmaf(A[e * KD + d], kd[d], s);
        Cp[e * KN + m] = s;
    }
}

__global__ void vt_gemm()
{
    int z = blockIdx.x;
    int h = z >> 6, t = (z >> 4) & 3, b = z & 15;
    int m = threadIdx.x;
    __shared__ float BT[KD * KD];
    __shared__ float bs[KD];
    for (int idx = m; idx < KD * KD; idx += 256) BT[idx] = g_dwT[idx];
    if (m < KD) bs[m] = g_db[m];
    __syncthreads();
    const float* vp = g_qkv + 2 * SZ_X + (long long)(h * KD) * COLS + t * TCOL + b * KN + m;
    float r[KD];
#pragma unroll
    for (int d = 0; d < KD; d++) r[d] = vp[(long long)d * COLS];
    float* Cp = g_vt + (long long)z * (KN * KD) + m * KD;
#pragma unroll
    for (int e = 0; e < KD; e++) {
        float s = bs[e];
#pragma unroll
        for (int d = 0; d < KD; d++) s = fmaf(r[d], BT[d * KD + e], s);
        Cp[e] = s;
    }
}

// ---------------- misc transforms ----------------
__global__ void make_vh(float* __restrict__ outv)   // v spikes -> output #2 layout [t,b,h,n,d]
{
    int i = blockIdx.x * blockDim.x + threadIdx.x;
    if (i >= SZ_X) return;
    int c = i >> 14, j = i & 16383;
    int t = j >> 12, b = (j >> 8) & 15, n = j & 255;
    int h = c / KD, d = c - h * KD;
    outv[(((long long)(t * KB + b) * KH + h) * KN + n) * KD + d] = g_qkv[2 * SZ_X + i];
}

__global__ void unhead(const float* __restrict__ x)
{
    int i = blockIdx.x * blockDim.x + threadIdx.x;
    if (i >= SZ_X) return;
    int c = i >> 14, j = i & 16383;
    int t = j >> 12, b = (j >> 8) & 15, n = j & 255;
    int h = c / KD, d = c - h * KD;
    long long oa = ((long long)(h * 64 + t * 16 + b) * KN + n) * KD + d;
    float xv = x[((long long)(t * KB + b) * KC + c) * KN + n];
    g_o[i] = g_oh[oa] + xv;
}

__global__ void final_lif(float* __restrict__ out)
{
    int i = blockIdx.x * blockDim.x + threadIdx.x;
    if (i >= SZ_XT) return;
    int c = i >> 12, j = i & 4095, b = j >> 8, n = j & 255;
    const float* p = g_p + (long long)c * COLS + j;
    float* o = out + ((long long)b * KC + c) * KN + n;
    float v = 0.f;
#pragma unroll
    for (int t = 0; t < KT; t++) {
        float xv = p[t * TCOL];
        v += (xv - v) * 0.5f;
        float s = (v >= 1.f) ? 1.f : 0.f;
        o[(long long)t * KB * KC * KN] = s;
        v *= (1.f - s);
    }
}

// ---------------- host launcher ----------------
extern "C" void kernel_launch(void* const* d_in, const int* in_sizes, int n_in,
                              void* d_out, int out_size)
{
    (void)in_sizes; (void)n_in; (void)out_size;
    const float* x    = (const float*)d_in[0];
    const float* wq   = (const float*)d_in[1];
    const float* wk   = (const float*)d_in[2];
    const float* wv   = (const float*)d_in[3];
    const float* kbn  = (const float*)d_in[4];
    const float* vbn  = (const float*)d_in[5];
    const float* dstw = (const float*)d_in[6];
    const float* dbn  = (const float*)d_in[7];
    const float* pw   = (const float*)d_in[8];
    const float* pb   = (const float*)d_in[9];
    const float* pbn  = (const float*)d_in[10];
    const float* timw = (const float*)d_in[11];
    const float* timb = (const float*)d_in[12];
    float* out   = (float*)d_out;
    float* out_v = out + SZ_X;

    float *pxs, *pqkv, *pcol, *pcb, *pkt, *pvt, *patt, *poh, *po, *pp;
    float *pwqkv, *pbqkv, *pwpf, *pbp, *pc1;
    cudaGetSymbolAddress((void**)&pxs,   g_xs);
    cudaGetSymbolAddress((void**)&pqkv,  g_qkv);
    cudaGetSymbolAddress((void**)&pcol,  g_col);
    cudaGetSymbolAddress((void**)&pcb,   g_cb);
    cudaGetSymbolAddress((void**)&pkt,   g_kt);
    cudaGetSymbolAddress((void**)&pvt,   g_vt);
    cudaGetSymbolAddress((void**)&patt,  g_attn);
    cudaGetSymbolAddress((void**)&poh,   g_oh);
    cudaGetSymbolAddress((void**)&po,    g_o);
    cudaGetSymbolAddress((void**)&pp,    g_p);
    cudaGetSymbolAddress((void**)&pwqkv, g_wqkv);
    cudaGetSymbolAddress((void**)&pbqkv, g_bqkv);
    cudaGetSymbolAddress((void**)&pwpf,  g_wpf);
    cudaGetSymbolAddress((void**)&pbp,   g_bp);
    cudaGetSymbolAddress((void**)&pc1,   g_c1);

    const int TB = 256;
    dim3 thr(16, 16);

    fold_weights<<<(3 * KC * KC + TB - 1) / TB, TB>>>(wq, wk, wv, pw, pb, kbn, vbn, pbn, dstw, dbn);
    lif_in<<<SZ_XT / TB, TB>>>(x);

    // fused q|k|v 1x1 conv: 1152 x 16384 x 384
    gemm_k<128,128,16,8,8,0><<<dim3(128, 9, 1), thr>>>(
        3 * KC, COLS, KC, pwqkv, KC, 0, 0, 0, pxs, COLS, 0, pqkv, COLS, 0, pbqkv);

    lif_blk<<<SZ_XT / TB, TB>>>(pqkv,            0.05f, SZ_XT, 12, nullptr);
    lif_blk<<<SZ_XT / TB, TB>>>(pqkv + SZ_X,     1.0f,  SZ_XT, 12, nullptr);
    lif_blk<<<SZ_XT / TB, TB>>>(pqkv + 2 * SZ_X, 1.0f,  SZ_XT, 12, nullptr);

    // TIM: sequential over t = 1..3
    tim_init<<<SZ_XT / TB, TB>>>();
    for (int ti = 1; ti < KT; ti++) {
        im2col_k<<<SZ_COL / TB, TB>>>();
        gemm_k<64,64,16,4,4,0><<<dim3(64, 6, 1), thr>>>(
            KC, TCOL, KC * 5, timw, KC * 5, 0, 0, 0, pcol, TCOL, 0, pcb, TCOL, 0, timb);
        tim_update<<<SZ_XT / TB, TB>>>(ti);
    }
    tim_final<<<SZ_XT / TB, TB>>>();
    c1_kernel<<<1, 1>>>();

    // dst conv + shared BN (z = h*64 + t*16 + b)
    kt_gemm<<<KT * KB * KH, 256>>>();
    vt_gemm<<<KT * KB * KH, 256>>>();
    make_vh<<<SZ_X / TB, TB>>>(out_v);

    // attention scores: per z, [256 x 256 x 48], A = q (K-major blocked, ATR=1)
    gemm_k<128,128,16,8,8,1><<<dim3(2, 2, 512), thr>>>(
        KN, KN, KD,
        pqkv, COLS, 6, (long long)KD * COLS, 256LL,
        pkt, KN, (long long)KD * KN,
        patt, KN, (long long)KN * KN, nullptr);

    lif_blk<<<ATT_T / TB, TB>>>(patt, 0.5f, ATT_T, 20, pc1);

    // out = attn_map @ v_t : per z, [256 x 48 x 256]
    gemm_k<128,48,16,8,3,0><<<dim3(1, 2, 512), thr>>>(
        KN, KD, KN,
        patt, KN, 0, (long long)KN * KN, 0,
        pvt, KD, (long long)KN * KD,
        poh, KD, (long long)KN * KD, nullptr);

    unhead<<<SZ_X / TB, TB>>>(x);

    // proj + folded BN: 384 x 16384 x 384
    gemm_k<128,128,16,8,8,0><<<dim3(128, 3, 1), thr>>>(
        KC, COLS, KC, pwpf, KC, 0, 0, 0, po, COLS, 0, pp, COLS, 0, pbp);

    final_lif<<<SZ_XT / TB, TB>>>(out);
}

// round 3
// speedup vs baseline: 3.1858x; 1.2525x over previous
#include <cuda_runtime.h>
#include <cuda_bf16.h>
#include <cstdint>

// ---------------- problem constants ----------------
constexpr int KT = 4, KB = 16, KC = 384, KN = 256, KH = 8, KD = 48;
constexpr int COLS = KT * KB * KN;     // 16384
constexpr int TCOL = KB * KN;          // 4096
constexpr int SZ_XT = KC * TCOL;       // 1,572,864
constexpr int SZ_X  = KC * COLS;       // 6,291,456
constexpr int ATT_T = KB * KH * KN * KN;              // 8,388,608
constexpr long long SZ_ATT = (long long)KT * ATT_T;   // 33,554,432
constexpr int SZ_COL = KC * 5 * TCOL;  // 7,864,320

// ---------------- device scratch ----------------
__device__ __align__(16) float g_qkv[3 * SZ_X];     // q|k|v fp32, blocked [c][t*4096+b*256+n]
__device__ __align__(16) float g_cb [SZ_XT];        // tim conv out (raw)
__device__ __align__(16) float g_attn[SZ_ATT];      // attn scores fp32 [z][n][m], z=h*64+t*16+b
__device__ __align__(16) float g_oh [SZ_X];         // attn out [z][n][d]
__device__ __align__(16) float g_o  [SZ_X];         // out + identity, blocked
__device__ __align__(16) float g_p  [SZ_X];         // proj pre-act, blocked

__device__ __align__(16) __nv_bfloat16 g_xsb [SZ_X];          // shortcut spikes bf16 [c][16384]
__device__ __align__(16) __nv_bfloat16 g_zt  [SZ_XT];         // tim z-state bf16 [c][4096]
__device__ __align__(16) __nv_bfloat16 g_colb[SZ_COL];        // im2col bf16 [1920][4096]
__device__ __align__(16) __nv_bfloat16 g_qh  [SZ_X];          // q heads bf16 [z][n][d]
__device__ __align__(16) __nv_bfloat16 g_amap[SZ_ATT];        // attn map bf16 [z][n][m]
__device__ __align__(16) __nv_bfloat16 g_wqkv3[3 * KC * 3 * KC];   // [1152][1152] splits along K
__device__ __align__(16) __nv_bfloat16 g_timw3[KC * 3 * KC * 5];   // [384][5760]
__device__ __align__(16) __nv_bfloat16 g_kt3[512 * 3 * KD * KN];   // [z][144][256]
__device__ __align__(16) __nv_bfloat16 g_vt3[512 * 3 * KN * KD];   // [z][768][48]

__device__ __align__(16) float g_wqkv[3 * KC * KC];
__device__ float g_bqkv[3 * KC];
__device__ __align__(16) float g_wpf[KC * KC];
__device__ float g_bp[KC];
__device__ float g_dw[KD * KD], g_dwT[KD * KD], g_db[KD];
__device__ float g_cnt[1], g_c1[1];

// ---------------- mma helpers ----------------
__device__ __forceinline__ void ldm_x4(uint32_t& r0, uint32_t& r1, uint32_t& r2, uint32_t& r3, uint32_t addr)
{
    asm volatile("ldmatrix.sync.aligned.m8n8.x4.shared.b16 {%0,%1,%2,%3}, [%4];"
                 : "=r"(r0), "=r"(r1), "=r"(r2), "=r"(r3) : "r"(addr));
}
__device__ __forceinline__ void ldm_x2t(uint32_t& r0, uint32_t& r1, uint32_t addr)
{
    asm volatile("ldmatrix.sync.aligned.m8n8.x2.trans.shared.b16 {%0,%1}, [%2];"
                 : "=r"(r0), "=r"(r1) : "r"(addr));
}
__device__ __forceinline__ void mma_bf16(float* c, const uint32_t* a, const uint32_t* b)
{
    asm volatile("mma.sync.aligned.m16n8k16.row.col.f32.bf16.bf16.f32 "
                 "{%0,%1,%2,%3}, {%4,%5,%6,%7}, {%8,%9}, {%0,%1,%2,%3};"
                 : "+f"(c[0]), "+f"(c[1]), "+f"(c[2]), "+f"(c[3])
                 : "r"(a[0]), "r"(a[1]), "r"(a[2]), "r"(a[3]), "r"(b[0]), "r"(b[1]));
}

// ---------------- bf16 tensor GEMM ----------------
// C[M,N](fp32) = A(bf16)[M,K'] * B(bf16)[K',N] (+bias per row).
// CYCA/CYCB: if nonzero, the k-offset into that operand wraps modulo CYC (element units).
template<int BM, int BN, int BK, int WM, int WN, int CYCA, int CYCB, int HASB>
__global__ void __launch_bounds__(256, 1)
gemm_bf16(int KTOT,
          const __nv_bfloat16* __restrict__ A, int lda, long long sA,
          const __nv_bfloat16* __restrict__ B, int ldb, long long sB,
          float* __restrict__ C, int ldc, long long sC,
          const float* __restrict__ bias)
{
    constexpr int NWM = BM / WM, NWN = BN / WN;
    constexpr int NW = NWM * NWN;
    static_assert(NW == 8, "8 warps");
    constexpr int NT = NW * 32;
    constexpr int MF = WM / 16, NF = WN / 8, KK = BK / 16;
    constexpr int APAD = 8, BPAD = 8;
    __shared__ __align__(16) __nv_bfloat16 As[2][BM][BK + APAD];
    __shared__ __align__(16) __nv_bfloat16 Bs[2][BK][BN + BPAD];

    const int tid = threadIdx.x;
    const int wid = tid >> 5, lane = tid & 31;
    const int wm = (wid / NWN) * WM, wn = (wid % NWN) * WN;
    const int row0 = blockIdx.y * BM, col0 = blockIdx.x * BN;
    const int z = blockIdx.z;
    A += (long long)z * sA;
    B += (long long)z * sB;
    C += (long long)z * sC;

    constexpr int A4 = BM * BK / 8, B4 = BK * BN / 8;
    constexpr int APT = (A4 + NT - 1) / NT, BPT = (B4 + NT - 1) / NT;
    uint4 ar[APT], br[BPT];
    const int ktiles = KTOT / BK;

    auto ldg = [&](int kt) {
        int ka = CYCA ? (kt % (CYCA / BK)) * BK : kt * BK;
        int kb = CYCB ? (kt % (CYCB / BK)) * BK : kt * BK;
#pragma unroll
        for (int u = 0; u < APT; u++) {
            int idx = tid + u * NT;
            if (A4 % NT == 0 || idx < A4) {
                int r = idx / (BK / 8), c8 = idx % (BK / 8);
                ar[u] = *(const uint4*)&A[(long long)(row0 + r) * lda + ka + c8 * 8];
            }
        }
#pragma unroll
        for (int u = 0; u < BPT; u++) {
            int idx = tid + u * NT;
            if (B4 % NT == 0 || idx < B4) {
                int r = idx / (BN / 8), c8 = idx % (BN / 8);
                br[u] = *(const uint4*)&B[(long long)(kb + r) * ldb + col0 + c8 * 8];
            }
        }
    };
    auto sts = [&](int buf) {
#pragma unroll
        for (int u = 0; u < APT; u++) {
            int idx = tid + u * NT;
            if (A4 % NT == 0 || idx < A4) {
                int r = idx / (BK / 8), c8 = idx % (BK / 8);
                *(uint4*)&As[buf][r][c8 * 8] = ar[u];
            }
        }
#pragma unroll
        for (int u = 0; u < BPT; u++) {
            int idx = tid + u * NT;
            if (B4 % NT == 0 || idx < B4) {
                int r = idx / (BN / 8), c8 = idx % (BN / 8);
                *(uint4*)&Bs[buf][r][c8 * 8] = br[u];
            }
        }
    };

    float acc[MF][NF][4];
#pragma unroll
    for (int i = 0; i < MF; i++)
#pragma unroll
        for (int j = 0; j < NF; j++)
#pragma unroll
            for (int q = 0; q < 4; q++) acc[i][j][q] = 0.f;

    auto comp = [&](int buf) {
#pragma unroll
        for (int kk = 0; kk < KK; kk++) {
            uint32_t af[MF][4], bf[NF][2];
#pragma unroll
            for (int mi = 0; mi < MF; mi++) {
                int row = wm + mi * 16 + (lane & 15);
                int col = kk * 16 + (lane >> 4) * 8;
                uint32_t ad = (uint32_t)__cvta_generic_to_shared(&As[buf][row][col]);
                ldm_x4(af[mi][0], af[mi][1], af[mi][2], af[mi][3], ad);
            }
#pragma unroll
            for (int nj = 0; nj < NF; nj++) {
                int r = kk * 16 + (lane & 15);
                int c = wn + nj * 8;
                uint32_t ad = (uint32_t)__cvta_generic_to_shared(&Bs[buf][r][c]);
                ldm_x2t(bf[nj][0], bf[nj][1], ad);
            }
#pragma unroll
            for (int mi = 0; mi < MF; mi++)
#pragma unroll
                for (int nj = 0; nj < NF; nj++)
                    mma_bf16(acc[mi][nj], af[mi], bf[nj]);
        }
    };

    ldg(0); sts(0); __syncthreads();
    int buf = 0;
    for (int kt = 1; kt < ktiles; kt++) {
        ldg(kt);
        comp(buf);
        sts(buf ^ 1);
        __syncthreads();
        buf ^= 1;
    }
    comp(buf);

#pragma unroll
    for (int mi = 0; mi < MF; mi++) {
        int r0 = row0 + wm + mi * 16 + (lane >> 2);
        float b0 = HASB ? bias[r0] : 0.f;
        float b1 = HASB ? bias[r0 + 8] : 0.f;
#pragma unroll
        for (int nj = 0; nj < NF; nj++) {
            int c0 = col0 + wn + nj * 8 + (lane & 3) * 2;
            float2 v0 = {acc[mi][nj][0] + b0, acc[mi][nj][1] + b0};
            float2 v1 = {acc[mi][nj][2] + b1, acc[mi][nj][3] + b1};
            *(float2*)&C[(long long)r0 * ldc + c0] = v0;
            *(float2*)&C[(long long)(r0 + 8) * ldc + c0] = v1;
        }
    }
}

// ---------------- fp32 GEMM (proj only) ----------------
template<int BM, int BN, int BK, int TM, int TN>
__global__ void __launch_bounds__(256, 2)
gemm_f32(int M, int N, int K,
         const float* __restrict__ A, int lda,
         const float* __restrict__ B, int ldb,
         float* __restrict__ C, int ldc,
         const float* __restrict__ bias)
{
    constexpr int TX = BN / TN, TY = BM / TM, NT = TX * TY;
    constexpr int A4 = BM * BK / 4, B4 = BK * BN / 4;
    constexpr int APT = A4 / NT, BPT = B4 / NT;
    __shared__ __align__(16) float As[2][BK][BM + 4];
    __shared__ __align__(16) float Bs[2][BK][BN];
    const int tx = threadIdx.x, ty = threadIdx.y;
    const int tid = ty * TX + tx;
    const int row0 = blockIdx.y * BM, col0 = blockIdx.x * BN;
    float4 aR[APT], bR[BPT];
    auto ldg = [&](int k0) {
#pragma unroll
        for (int u = 0; u < APT; u++) {
            int idx = tid + u * NT;
            int r = idx / (BK / 4), c4 = idx % (BK / 4);
            aR[u] = *(const float4*)&A[(long long)(row0 + r) * lda + k0 + c4 * 4];
        }
#pragma unroll
        for (int u = 0; u < BPT; u++) {
            int idx = tid + u * NT;
            int kk = idx / (BN / 4), n4 = idx % (BN / 4);
            bR[u] = *(const float4*)&B[(long long)(k0 + kk) * ldb + col0 + n4 * 4];
        }
    };
    auto sts = [&](int buf) {
#pragma unroll
        for (int u = 0; u < APT; u++) {
            int idx = tid + u * NT;
            int r = idx / (BK / 4), c4 = idx % (BK / 4);
            As[buf][c4 * 4 + 0][r] = aR[u].x;
            As[buf][c4 * 4 + 1][r] = aR[u].y;
            As[buf][c4 * 4 + 2][r] = aR[u].z;
            As[buf][c4 * 4 + 3][r] = aR[u].w;
        }
#pragma unroll
        for (int u = 0; u < BPT; u++) {
            int idx = tid + u * NT;
            int kk = idx / (BN / 4), n4 = idx % (BN / 4);
            *(float4*)&Bs[buf][kk][n4 * 4] = bR[u];
        }
    };
    float acc[TM][TN];
#pragma unroll
    for (int i = 0; i < TM; i++)
#pragma unroll
        for (int j = 0; j < TN; j++) acc[i][j] = 0.f;
    auto comp = [&](int buf) {
#pragma unroll
        for (int kk = 0; kk < BK; kk++) {
            float a[TM], b[TN];
#pragma unroll
            for (int i4 = 0; i4 < TM / 4; i4++) {
                float4 v = *(const float4*)&As[buf][kk][ty * TM + i4 * 4];
                a[i4*4+0]=v.x; a[i4*4+1]=v.y; a[i4*4+2]=v.z; a[i4*4+3]=v.w;
            }
#pragma unroll
            for (int j4 = 0; j4 < TN / 4; j4++) {
                float4 v = *(const float4*)&Bs[buf][kk][tx * TN + j4 * 4];
                b[j4*4+0]=v.x; b[j4*4+1]=v.y; b[j4*4+2]=v.z; b[j4*4+3]=v.w;
            }
#pragma unroll
            for (int i = 0; i < TM; i++)
#pragma unroll
                for (int j = 0; j < TN; j++)
                    acc[i][j] = fmaf(a[i], b[j], acc[i][j]);
        }
    };
    ldg(0); sts(0); __syncthreads();
    const int nit = K / BK;
    int buf = 0;
    for (int it = 1; it < nit; it++) {
        ldg(it * BK); comp(buf); sts(buf ^ 1); __syncthreads(); buf ^= 1;
    }
    comp(buf);
#pragma unroll
    for (int i = 0; i < TM; i++) {
        int r = row0 + ty * TM + i;
        float bv = bias ? bias[r] : 0.f;
#pragma unroll
        for (int j4 = 0; j4 < TN / 4; j4++) {
            float4 v;
            v.x = acc[i][j4*4+0] + bv; v.y = acc[i][j4*4+1] + bv;
            v.z = acc[i][j4*4+2] + bv; v.w = acc[i][j4*4+3] + bv;
            *(float4*)&C[(long long)r * ldc + col0 + tx * TN + j4 * 4] = v;
        }
    }
}

// ---------------- split helper ----------------
__device__ __forceinline__ void split3f(float x, __nv_bfloat16& h, __nv_bfloat16& m, __nv_bfloat16& l)
{
    __nv_bfloat16 bh = __float2bfloat16(x);
    float r1 = x - __bfloat162float(bh);
    __nv_bfloat16 bm = __float2bfloat16(r1);
    float r2 = r1 - __bfloat162float(bm);
    h = bh; m = bm; l = __float2bfloat16(r2);
}

// ---------------- BN folding ----------------
__global__ void fold_weights(const float* __restrict__ wq, const float* __restrict__ wk,
                             const float* __restrict__ wv, const float* __restrict__ pw,
                             const float* __restrict__ pb, const float* __restrict__ kbn,
                             const float* __restrict__ vbn, const float* __restrict__ pbn,
                             const float* __restrict__ dstw, const float* __restrict__ dbn)
{
    int i = blockIdx.x * blockDim.x + threadIdx.x;
    if (i == 0) g_cnt[0] = 0.f;
    if (i < 3 * KC * KC) {
        int rr = i / KC, c = i % KC;
        float w;
        if (rr < KC) w = wq[rr * KC + c];
        else if (rr < 2 * KC) { int d = rr - KC;     w = kbn[d] * rsqrtf(kbn[3*KC + d] + 1e-5f) * wk[d * KC + c]; }
        else                  { int d = rr - 2 * KC; w = vbn[d] * rsqrtf(vbn[3*KC + d] + 1e-5f) * wv[d * KC + c]; }
        g_wqkv[i] = w;
    }
    if (i < KC * KC) {
        int d = i / KC;
        g_wpf[i] = pbn[d] * rsqrtf(pbn[3*KC + d] + 1e-5f) * pw[i];
    }
    if (i < 3 * KC) {
        float bvv;
        if (i < KC) bvv = 0.f;
        else if (i < 2 * KC) { int d = i - KC;     float inv = kbn[d] * rsqrtf(kbn[3*KC+d] + 1e-5f); bvv = kbn[KC + d] - inv * kbn[2*KC + d]; }
        else                 { int d = i - 2 * KC; float inv = vbn[d] * rsqrtf(vbn[3*KC+d] + 1e-5f); bvv = vbn[KC + d] - inv * vbn[2*KC + d]; }
        g_bqkv[i] = bvv;
    }
    if (i < KC) {
        float inv = pbn[i] * rsqrtf(pbn[3*KC + i] + 1e-5f);
        g_bp[i] = pbn[KC + i] + inv * (pb[i] - pbn[2*KC + i]);
    }
    if (i < KD * KD) {
        int e = i / KD, d = i % KD;
        float inv = dbn[e] * rsqrtf(dbn[3*KD + e] + 1e-5f);
        float wf = inv * dstw[i];
        g_dw[i] = wf;
        g_dwT[d * KD + e] = wf;
    }
    if (i < KD) {
        float inv = dbn[i] * rsqrtf(dbn[3*KD + i] + 1e-5f);
        g_db[i] = dbn[KD + i] - inv * dbn[2*KD + i];
    }
}

// split qkv weights: [1152][384] -> bf16 [1152][1152] (3 splits concat along K)
__global__ void split_qkv()
{
    int i = blockIdx.x * blockDim.x + threadIdx.x;
    if (i >= 3 * KC * KC) return;
    int r = i / KC, c = i % KC;
    __nv_bfloat16 h, m, l;
    split3f(g_wqkv[i], h, m, l);
    __nv_bfloat16* row = g_wqkv3 + (long long)r * (3 * KC);
    row[c] = h; row[KC + c] = m; row[2 * KC + c] = l;
}

// split tim weights: [384][1920] -> [384][5760]
__global__ void split_tim(const float* __restrict__ timw)
{
    int i = blockIdx.x * blockDim.x + threadIdx.x;
    if (i >= KC * KC * 5) return;
    int r = i / (KC * 5), c = i % (KC * 5);
    __nv_bfloat16 h, m, l;
    split3f(timw[i], h, m, l);
    __nv_bfloat16* row = g_timw3 + (long long)r * (3 * KC * 5);
    row[c] = h; row[KC * 5 + c] = m; row[2 * KC * 5 + c] = l;
}

// ---------------- LIF kernels ----------------
__global__ void lif_in(const float* __restrict__ x)
{
    int i = blockIdx.x * blockDim.x + threadIdx.x;
    if (i >= SZ_XT) return;
    int c = i >> 12, j = i & 4095, b = j >> 8, n = j & 255;
    const float* xp = x + ((long long)b * KC + c) * KN + n;
    __nv_bfloat16* o = g_xsb + (long long)c * COLS + j;
    float v = 0.f;
#pragma unroll
    for (int t = 0; t < KT; t++) {
        float xv = xp[(long long)t * KB * KC * KN];
        v += (xv - v) * 0.5f;
        float s = (v >= 1.f) ? 1.f : 0.f;
        o[t * TCOL] = __float2bfloat16(s);
        v *= (1.f - s);
    }
}

__global__ void lif_blk(float* __restrict__ buf, float vth, int per_t, int lg)
{
    int i = blockIdx.x * blockDim.x + threadIdx.x;
    if (i >= per_t) return;
    long long inner = 1LL << lg;
    long long o = ((long long)(i >> lg)) * (inner * KT) + (i & ((int)inner - 1));
    float v = 0.f;
#pragma unroll
    for (int t = 0; t < KT; t++) {
        long long a = o + (long long)t * inner;
        float xv = buf[a];
        v += (xv - v) * 0.5f;
        float s = (v >= vth) ? 1.f : 0.f;
        buf[a] = s;
        v *= (1.f - s);
    }
}

// attn lif: fp32 in (scaled by c1), bf16 binary out
__global__ void lif_attn()
{
    int i = blockIdx.x * blockDim.x + threadIdx.x;
    if (i >= ATT_T) return;
    long long inner = 1LL << 20;
    long long o = ((long long)(i >> 20)) * (inner * KT) + (i & ((1 << 20) - 1));
    float c = g_c1[0];
    float v = 0.f;
#pragma unroll
    for (int t = 0; t < KT; t++) {
        long long a = o + (long long)t * inner;
        float xv = g_attn[a] * c;
        v += (xv - v) * 0.5f;
        float s = (v >= 0.5f) ? 1.f : 0.f;
        g_amap[a] = __float2bfloat16(s);
        v *= (1.f - s);
    }
}

// ---------------- TIM ----------------
__global__ void tim_init()
{
    int i = blockIdx.x * blockDim.x + threadIdx.x;
    if (i >= SZ_XT) return;
    int c = i >> 12, j = i & 4095;
    float q = g_qkv[(long long)c * COLS + j];
    g_zt[i] = __float2bfloat16(5.0f * q);   // 0.2 * 5q = q (binary)
}

__global__ void im2col_k()
{
    int i = blockIdx.x * blockDim.x + threadIdx.x;
    if (i >= SZ_COL) return;
    int j = i & 4095, r = i >> 12;
    int kk = r % 5, ci = r / 5;
    int n = j & 255;
    int n2 = n + kk - 2;
    __nv_bfloat16 v = __float2bfloat16(0.f);
    if (n2 >= 0 && n2 < KN) v = g_zt[ci * TCOL + (j - n) + n2];
    g_colb[i] = v;
}

__global__ void tim_update(int ti, const float* __restrict__ timb)
{
    int i = blockIdx.x * blockDim.x + threadIdx.x;
    if (i >= SZ_XT) return;
    int c = i >> 12, j = i & 4095;
    float cv = 0.2f * g_cb[i] + timb[c];
    float s = (cv * 0.5f >= 0.3f) ? 1.f : 0.f;
    long long qa = (long long)c * COLS + ti * TCOL + j;
    float q = g_qkv[qa];
    float xt = s * 0.6f + q * 0.4f;
    g_qkv[qa] = xt;
    g_zt[i] = __float2bfloat16(3.0f * s + 2.0f * q);
}

__global__ void tim_final()
{
    int i = blockIdx.x * blockDim.x + threadIdx.x;
    int cnt = 0;
    if (i < SZ_XT) {
        int c = i >> 12, j = i & 4095;
        float* q = g_qkv + (long long)c * COLS + j;
        float v = 0.f;
#pragma unroll
        for (int t = 0; t < KT; t++) {
            float xv = q[t * TCOL];
            v += (xv - v) * 0.5f;
            float s = (v >= 0.5f) ? 1.f : 0.f;
            q[t * TCOL] = s;
            cnt += (int)s;
            v *= (1.f - s);
        }
    }
#pragma unroll
    for (int o = 16; o > 0; o >>= 1) cnt += __shfl_down_sync(0xffffffffu, cnt, o);
    if ((threadIdx.x & 31) == 0 && cnt) atomicAdd(&g_cnt[0], (float)cnt);
}

__global__ void c1_kernel()
{
    float mean = g_cnt[0] / 6291456.0f;
    g_c1[0] = fminf(1.0f / sqrtf(mean * 48.0f + 1e-6f), 10.0f);
}

// ---------------- dst conv (48x48) with 3-split bf16 epilogue ----------------
__global__ void kt_gemm()
{
    int z = blockIdx.x;                 // z = h*64 + t*16 + b
    int h = z >> 6, t = (z >> 4) & 3, b = z & 15;
    int m = threadIdx.x;
    __shared__ float A[KD * KD];
    __shared__ float bs[KD];
    for (int idx = m; idx < KD * KD; idx += 256) A[idx] = g_dw[idx];
    if (m < KD) bs[m] = g_db[m];
    __syncthreads();
    const float* kp = g_qkv + SZ_X + (long long)(h * KD) * COLS + t * TCOL + b * KN + m;
    float kd[KD];
#pragma unroll
    for (int d = 0; d < KD; d++) kd[d] = kp[(long long)d * COLS];
    __nv_bfloat16* Cp = g_kt3 + (long long)z * (3 * KD * KN);
#pragma unroll
    for (int e = 0; e < KD; e++) {
        float s = bs[e];
#pragma unroll
        for (int d = 0; d < KD; d++) s = fmaf(A[e * KD + d], kd[d], s);
        __nv_bfloat16 hh, mm, ll;
        split3f(s, hh, mm, ll);
        Cp[e * KN + m] = hh;
        Cp[(KD + e) * KN + m] = mm;
        Cp[(2 * KD + e) * KN + m] = ll;
    }
}

__global__ void vt_gemm()
{
    int z = blockIdx.x;
    int h = z >> 6, t = (z >> 4) & 3, b = z & 15;
    int m = threadIdx.x;
    __shared__ float BT[KD * KD];
    __shared__ float bs[KD];
    for (int idx = m; idx < KD * KD; idx += 256) BT[idx] = g_dwT[idx];
    if (m < KD) bs[m] = g_db[m];
    __syncthreads();
    const float* vp = g_qkv + 2 * SZ_X + (long long)(h * KD) * COLS + t * TCOL + b * KN + m;
    float r[KD];
#pragma unroll
    for (int d = 0; d < KD; d++) r[d] = vp[(long long)d * COLS];
    __nv_bfloat16* Cp = g_vt3 + (long long)z * (3 * KN * KD);
#pragma unroll
    for (int e = 0; e < KD; e++) {
        float s = bs[e];
#pragma unroll
        for (int d = 0; d < KD; d++) s = fmaf(r[d], BT[d * KD + e], s);
        __nv_bfloat16 hh, mm, ll;
        split3f(s, hh, mm, ll);
        Cp[m * KD + e] = hh;
        Cp[(KN + m) * KD + e] = mm;
        Cp[(2 * KN + m) * KD + e] = ll;
    }
}

// ---------------- misc transforms ----------------
__global__ void make_qh()   // q spikes (fp32 blocked) -> bf16 [z][n][d]
{
    int i = blockIdx.x * blockDim.x + threadIdx.x;
    if (i >= SZ_X) return;
    int d = i % KD;
    int n = (i / KD) % KN;
    int z = i / (KD * KN);
    int h = z >> 6, t = (z >> 4) & 3, b = z & 15;
    float q = g_qkv[(long long)(h * KD + d) * COLS + t * TCOL + b * KN + n];
    g_qh[i] = __float2bfloat16(q);
}

__global__ void make_vh(float* __restrict__ outv)   // v spikes -> output #2 [t,b,h,n,d]
{
    int i = blockIdx.x * blockDim.x + threadIdx.x;
    if (i >= SZ_X) return;
    int c = i >> 14, j = i & 16383;
    int t = j >> 12, b = (j >> 8) & 15, n = j & 255;
    int h = c / KD, d = c - h * KD;
    outv[(((long long)(t * KB + b) * KH + h) * KN + n) * KD + d] = g_qkv[2 * SZ_X + i];
}

__global__ void unhead(const float* __restrict__ x)
{
    int i = blockIdx.x * blockDim.x + threadIdx.x;
    if (i >= SZ_X) return;
    int c = i >> 14, j = i & 16383;
    int t = j >> 12, b = (j >> 8) & 15, n = j & 255;
    int h = c / KD, d = c - h * KD;
    long long oa = ((long long)(h * 64 + t * 16 + b) * KN + n) * KD + d;
    float xv = x[((long long)(t * KB + b) * KC + c) * KN + n];
    g_o[i] = g_oh[oa] + xv;
}

__global__ void final_lif(float* __restrict__ out)
{
    int i = blockIdx.x * blockDim.x + threadIdx.x;
    if (i >= SZ_XT) return;
    int c = i >> 12, j = i & 4095, b = j >> 8, n = j & 255;
    const float* p = g_p + (long long)c * COLS + j;
    float* o = out + ((long long)b * KC + c) * KN + n;
    float v = 0.f;
#pragma unroll
    for (int t = 0; t < KT; t++) {
        float xv = p[t * TCOL];
        v += (xv - v) * 0.5f;
        float s = (v >= 1.f) ? 1.f : 0.f;
        o[(long long)t * KB * KC * KN] = s;
        v *= (1.f - s);
    }
}

// ---------------- host launcher ----------------
extern "C" void kernel_launch(void* const* d_in, const int* in_sizes, int n_in,
                              void* d_out, int out_size)
{
    (void)in_sizes; (void)n_in; (void)out_size;
    const float* x    = (const float*)d_in[0];
    const float* wq   = (const float*)d_in[1];
    const float* wk   = (const float*)d_in[2];
    const float* wv   = (const float*)d_in[3];
    const float* kbn  = (const float*)d_in[4];
    const float* vbn  = (const float*)d_in[5];
    const float* dstw = (const float*)d_in[6];
    const float* dbn  = (const float*)d_in[7];
    const float* pw   = (const float*)d_in[8];
    const float* pb   = (const float*)d_in[9];
    const float* pbn  = (const float*)d_in[10];
    const float* timw = (const float*)d_in[11];
    const float* timb = (const float*)d_in[12];
    float* out   = (float*)d_out;
    float* out_v = out + SZ_X;

    float *pqkv, *pcb, *patt, *poh, *po, *pp, *pwpf, *pbp, *pbqkv;
    __nv_bfloat16 *pxsb, *pcolb, *pqh, *pamap, *pwqkv3, *ptimw3, *pkt3, *pvt3;
    cudaGetSymbolAddress((void**)&pqkv,   g_qkv);
    cudaGetSymbolAddress((void**)&pcb,    g_cb);
    cudaGetSymbolAddress((void**)&patt,   g_attn);
    cudaGetSymbolAddress((void**)&poh,    g_oh);
    cudaGetSymbolAddress((void**)&po,     g_o);
    cudaGetSymbolAddress((void**)&pp,     g_p);
    cudaGetSymbolAddress((void**)&pwpf,   g_wpf);
    cudaGetSymbolAddress((void**)&pbp,    g_bp);
    cudaGetSymbolAddress((void**)&pbqkv,  g_bqkv);
    cudaGetSymbolAddress((void**)&pxsb,   g_xsb);
    cudaGetSymbolAddress((void**)&pcolb,  g_colb);
    cudaGetSymbolAddress((void**)&pqh,    g_qh);
    cudaGetSymbolAddress((void**)&pamap,  g_amap);
    cudaGetSymbolAddress((void**)&pwqkv3, g_wqkv3);
    cudaGetSymbolAddress((void**)&ptimw3, g_timw3);
    cudaGetSymbolAddress((void**)&pkt3,   g_kt3);
    cudaGetSymbolAddress((void**)&pvt3,   g_vt3);

    const int TB = 256;

    fold_weights<<<(3 * KC * KC + TB - 1) / TB, TB>>>(wq, wk, wv, pw, pb, kbn, vbn, pbn, dstw, dbn);
    split_qkv<<<(3 * KC * KC + TB - 1) / TB, TB>>>();
    split_tim<<<(KC * KC * 5 + TB - 1) / TB, TB>>>(timw);
    lif_in<<<SZ_XT / TB, TB>>>(x);

    // fused q|k|v: M=1152, N=16384, K'=1152 (3 splits), B wraps every 384
    gemm_bf16<128,128,32,64,32,0,384,1><<<dim3(128, 9, 1), 256>>>(
        1152, pwqkv3, 1152, 0, pxsb, COLS, 0, pqkv, COLS, 0, pbqkv);

    lif_blk<<<SZ_XT / TB, TB>>>(pqkv,            0.05f, SZ_XT, 12);
    lif_blk<<<SZ_XT / TB, TB>>>(pqkv + SZ_X,     1.0f,  SZ_XT, 12);
    lif_blk<<<SZ_XT / TB, TB>>>(pqkv + 2 * SZ_X, 1.0f,  SZ_XT, 12);

    // TIM: sequential over t = 1..3
    tim_init<<<SZ_XT / TB, TB>>>();
    for (int ti = 1; ti < KT; ti++) {
        im2col_k<<<SZ_COL / TB, TB>>>();
        // M=384, N=4096, K'=5760 (3 splits), B wraps every 1920
        gemm_bf16<64,128,32,32,32,0,1920,0><<<dim3(32, 6, 1), 256>>>(
            5760, ptimw3, 5760, 0, pcolb, TCOL, 0, pcb, TCOL, 0, nullptr);
        tim_update<<<SZ_XT / TB, TB>>>(ti, timb);
    }
    tim_final<<<SZ_XT / TB, TB>>>();
    c1_kernel<<<1, 1>>>();

    // dst conv + shared BN, 3-split bf16 outputs (z = h*64 + t*16 + b)
    kt_gemm<<<KT * KB * KH, 256>>>();
    vt_gemm<<<KT * KB * KH, 256>>>();
    make_qh<<<SZ_X / TB, TB>>>();
    make_vh<<<SZ_X / TB, TB>>>(out_v);

    // attention scores: per z, M=256, N=256, K'=144 (3 splits of k_t), A=q wraps every 48
    gemm_bf16<128,128,16,64,32,48,0,0><<<dim3(2, 2, 512), 256>>>(
        144, pqh, 48, (long long)KN * KD,
        pkt3, KN, (long long)3 * KD * KN,
        patt, KN, (long long)KN * KN, nullptr);

    lif_attn<<<ATT_T / TB, TB>>>();

    // out = attn_map @ v_t: per z, M=256, N=48, K'=768 (3 splits), A wraps every 256
    gemm_bf16<128,48,32,32,24,256,0,0><<<dim3(1, 2, 512), 256>>>(
        768, pamap, KN, (long long)KN * KN,
        pvt3, KD, (long long)3 * KN * KD,
        poh, KD, (long long)KN * KD, nullptr);

    unhead<<<SZ_X / TB, TB>>>(x);

    // proj (fp32 FFMA): 384 x 16384 x 384
    gemm_f32<128,128,16,8,8><<<dim3(128, 3, 1), dim3(16, 16)>>>(
        KC, COLS, KC, pwpf, KC, po, COLS, pp, COLS, pbp);

    final_lif<<<SZ_XT / TB, TB>>>(out);
}